// round 4
// baseline (speedup 1.0000x reference)
#include <cuda_runtime.h>
#include <cuda_bf16.h>
#include <cstdint>

#define N_NODES 100000
#define N_EDGES 1200000
#define D 64
#define KEEP_PROB 0.7f

// Scratch: layer outputs (25.6 MB each). __device__ globals per alloc rules.
__device__ float g_x1[(size_t)N_NODES * D];
__device__ float g_x2[(size_t)N_NODES * D];

// ---------------------------------------------------------------------------
// Zero both scratch buffers (float4 stores, grid-stride).
// ---------------------------------------------------------------------------
__global__ void zero_kernel() {
    const size_t total4 = (size_t)N_NODES * D / 4;  // per buffer
    float4 z = make_float4(0.f, 0.f, 0.f, 0.f);
    float4* p1 = reinterpret_cast<float4*>(g_x1);
    float4* p2 = reinterpret_cast<float4*>(g_x2);
    for (size_t i = blockIdx.x * (size_t)blockDim.x + threadIdx.x;
         i < total4; i += (size_t)gridDim.x * blockDim.x) {
        p1[i] = z;
        p2[i] = z;
    }
}

// ---------------------------------------------------------------------------
// FC: out[n][d] = sum_k emb[n][k] * W[d][k] + b[d]
// Block = 256 threads = 4 nodes x 64 dims. W cached in smem with +1 pad row.
// ---------------------------------------------------------------------------
__global__ void fc_kernel(const float* __restrict__ emb,
                          const float* __restrict__ W,
                          const float* __restrict__ b,
                          float* __restrict__ out) {
    __shared__ float Ws[64 * 65];
    __shared__ float bs[64];
    __shared__ float es[4 * 64];

    int tid = threadIdx.x;
    #pragma unroll
    for (int i = tid; i < 64 * 64; i += 256) {
        int d = i >> 6, k = i & 63;
        Ws[d * 65 + k] = W[i];
    }
    if (tid < 64) bs[tid] = b[tid];

    int n0 = blockIdx.x * 4;
    es[tid] = emb[(size_t)n0 * D + tid];  // 256 contiguous floats = 4 rows
    __syncthreads();

    int nl = tid >> 6;
    int d  = tid & 63;
    const float* er = &es[nl * 64];
    const float* wr = &Ws[d * 65];
    float sum = bs[d];
    #pragma unroll
    for (int k = 0; k < 64; k++) sum = fmaf(er[k], wr[k], sum);
    out[(size_t)(n0 + nl) * D + d] = sum;
}

// ---------------------------------------------------------------------------
// SpMM with edge dropout: y[rows[e]] += (keep ? vals[e]/0.7 : 0) * x[cols[e]]
// 2 edges per warp: lanes 0-15 edge e, lanes 16-31 edge e+1.
// Each lane handles one float4 (16 B) of the 256 B row.
// Scatter via red.global.add.v4.f32 (no-return REDG).
// ---------------------------------------------------------------------------
__global__ void spmm_kernel(const float* __restrict__ x,
                            float* __restrict__ y,
                            const float* __restrict__ vals,
                            const float* __restrict__ dropu,
                            const int* __restrict__ rows,
                            const int* __restrict__ cols) {
    int gwarp = (blockIdx.x * blockDim.x + threadIdx.x) >> 5;
    int lane  = threadIdx.x & 31;
    int e = gwarp * 2 + (lane >> 4);
    if (e >= N_EDGES) return;

    float u = dropu[e];
    // keep iff (u + 0.7) >= 1.0, computed in fp32 like the reference
    if (u + KEEP_PROB < 1.0f) return;
    float v = vals[e] / KEEP_PROB;

    int c = cols[e];
    int r = rows[e];
    int l = lane & 15;

    const float4* xs = reinterpret_cast<const float4*>(x + (size_t)c * D);
    float4 m = xs[l];
    m.x *= v; m.y *= v; m.z *= v; m.w *= v;

    float* dst = y + (size_t)r * D + l * 4;
    asm volatile("red.global.add.v4.f32 [%0], {%1,%2,%3,%4};"
                 :: "l"(dst), "f"(m.x), "f"(m.y), "f"(m.z), "f"(m.w)
                 : "memory");
}

// ---------------------------------------------------------------------------
// Finalize: out = (fc + x1 + x2) / 3
// ---------------------------------------------------------------------------
__global__ void finalize_kernel(float* __restrict__ out) {
    const size_t total4 = (size_t)N_NODES * D / 4;
    const float4* a = reinterpret_cast<const float4*>(g_x1);
    const float4* b = reinterpret_cast<const float4*>(g_x2);
    float4* o = reinterpret_cast<float4*>(out);
    const float s = 1.0f / 3.0f;
    for (size_t i = blockIdx.x * (size_t)blockDim.x + threadIdx.x;
         i < total4; i += (size_t)gridDim.x * blockDim.x) {
        float4 ov = o[i];
        float4 av = a[i];
        float4 bv = b[i];
        ov.x = (ov.x + av.x + bv.x) * s;
        ov.y = (ov.y + av.y + bv.y) * s;
        ov.z = (ov.z + av.z + bv.z) * s;
        ov.w = (ov.w + av.w + bv.w) * s;
        o[i] = ov;
    }
}

extern "C" void kernel_launch(void* const* d_in, const int* in_sizes, int n_in,
                              void* d_out, int out_size) {
    const float* all_emb = (const float*)d_in[0];
    const float* W       = (const float*)d_in[1];
    const float* b       = (const float*)d_in[2];
    const float* vals    = (const float*)d_in[3];
    const float* drop_u  = (const float*)d_in[4];
    const int*   rows    = (const int*)d_in[5];
    const int*   cols    = (const int*)d_in[6];
    float* out = (float*)d_out;

    float* x1;
    float* x2;
    cudaGetSymbolAddress((void**)&x1, g_x1);
    cudaGetSymbolAddress((void**)&x2, g_x2);

    // 1) zero scratch
    zero_kernel<<<1184, 256>>>();

    // 2) fc -> out (unscaled)
    fc_kernel<<<N_NODES / 4, 256>>>(all_emb, W, b, out);

    // 3) layer 0: x1 = A0 @ all_emb
    {
        int warps = (N_EDGES + 1) / 2;
        int blocks = (warps * 32 + 255) / 256;
        spmm_kernel<<<blocks, 256>>>(all_emb, x1, vals, drop_u, rows, cols);
    }

    // 4) layer 1: x2 = A1 @ x1
    {
        int warps = (N_EDGES + 1) / 2;
        int blocks = (warps * 32 + 255) / 256;
        spmm_kernel<<<blocks, 256>>>(x1, x2, vals, drop_u + N_EDGES, rows, cols);
    }

    // 5) out = (out + x1 + x2) / 3
    finalize_kernel<<<1184, 256>>>(out);
}

// round 8
// speedup vs baseline: 1.5388x; 1.5388x over previous
#include <cuda_runtime.h>
#include <cuda_bf16.h>
#include <cstdint>

#define N_NODES 100000
#define N_EDGES 1200000
#define D 64
#define KEEP_PROB 0.7f
#define SCAN_CHUNK 2048
#define NUM_SBLK ((N_NODES + SCAN_CHUNK - 1) / SCAN_CHUNK)  // 49

typedef unsigned long long ull;

// ---------------------------------------------------------------------------
// Scratch (__device__ globals per alloc rules).
// Packed layout: low 32 bits = layer 0, high 32 bits = layer 1. Counts/offsets
// never exceed 1.2M so the halves can be counted/scanned/cursored as one u64
// with no carry between halves.
// ---------------------------------------------------------------------------
__device__ ull  g_cnt[N_NODES];        // per-row kept-edge counts (packed)
__device__ ull  g_off[N_NODES + 1];    // exclusive prefix (packed)
__device__ ull  g_cur[N_NODES];        // scatter cursors (packed)
__device__ ull  g_bsum[NUM_SBLK];      // scan block sums
__device__ int2 g_e0[N_EDGES];         // layer-0 CSR payload: {col, bits(val/0.7)}
__device__ int2 g_e1[N_EDGES];         // layer-1 CSR payload
__device__ float g_x1[(size_t)N_NODES * D];  // layer-0 output

// ---------------------------------------------------------------------------
// 1) zero the packed counters
// ---------------------------------------------------------------------------
__global__ void zero_cnt_kernel() {
    int i = blockIdx.x * blockDim.x + threadIdx.x;
    if (i < N_NODES) g_cnt[i] = 0ULL;
}

// ---------------------------------------------------------------------------
// 2) count kept edges per row for both layers with ONE packed 64-bit atomic
// ---------------------------------------------------------------------------
__global__ void count_kernel(const int* __restrict__ rows,
                             const float* __restrict__ du) {
    int e = blockIdx.x * blockDim.x + threadIdx.x;
    if (e >= N_EDGES) return;
    float u0 = du[e];
    float u1 = du[N_EDGES + e];
    ull add = 0ULL;
    if (u0 + KEEP_PROB >= 1.0f) add += 1ULL;
    if (u1 + KEEP_PROB >= 1.0f) add += (1ULL << 32);
    if (add) atomicAdd(&g_cnt[rows[e]], add);
}

// ---------------------------------------------------------------------------
// 3) exclusive scan of packed counts: part -> top -> add (+cursor init)
// ---------------------------------------------------------------------------
__global__ void scan_part_kernel() {
    __shared__ ull wt[8];
    __shared__ ull wtot;
    int tid = threadIdx.x;
    int lane = tid & 31, wid = tid >> 5;
    int base = blockIdx.x * SCAN_CHUNK + tid * 8;

    ull v[8]; ull sum = 0ULL;
    #pragma unroll
    for (int j = 0; j < 8; j++) {
        int idx = base + j;
        v[j] = (idx < N_NODES) ? g_cnt[idx] : 0ULL;
        sum += v[j];
    }
    // warp inclusive scan of per-thread sums
    ull s = sum;
    #pragma unroll
    for (int o = 1; o < 32; o <<= 1) {
        ull t = __shfl_up_sync(0xffffffffu, s, o);
        if (lane >= o) s += t;
    }
    if (lane == 31) wt[wid] = s;
    __syncthreads();
    if (tid == 0) {
        ull r = 0ULL;
        #pragma unroll
        for (int k = 0; k < 8; k++) { ull t = wt[k]; wt[k] = r; r += t; }
        wtot = r;
    }
    __syncthreads();

    ull run = wt[wid] + (s - sum);  // exclusive offset for this thread's chunk
    #pragma unroll
    for (int j = 0; j < 8; j++) {
        int idx = base + j;
        if (idx < N_NODES) g_off[idx] = run;
        run += v[j];
    }
    if (tid == 0) g_bsum[blockIdx.x] = wtot;
}

__global__ void scan_top_kernel() {
    __shared__ ull s[NUM_SBLK];
    int tid = threadIdx.x;
    if (tid < NUM_SBLK) s[tid] = g_bsum[tid];
    __syncthreads();
    if (tid == 0) {
        ull r = 0ULL;
        for (int k = 0; k < NUM_SBLK; k++) { ull t = s[k]; g_bsum[k] = r; r += t; }
        g_off[N_NODES] = r;  // grand totals (packed)
    }
}

__global__ void scan_add_kernel() {
    int i = blockIdx.x * blockDim.x + threadIdx.x;
    if (i < N_NODES) {
        ull o = g_off[i] + g_bsum[i / SCAN_CHUNK];
        g_off[i] = o;
        g_cur[i] = o;  // init scatter cursors
    }
}

// ---------------------------------------------------------------------------
// 4) scatter kept edges into per-layer CSR slots (packed cursor atomic)
// ---------------------------------------------------------------------------
__global__ void scatter_kernel(const int* __restrict__ rows,
                               const int* __restrict__ cols,
                               const float* __restrict__ vals,
                               const float* __restrict__ du) {
    int e = blockIdx.x * blockDim.x + threadIdx.x;
    if (e >= N_EDGES) return;
    float u0 = du[e];
    float u1 = du[N_EDGES + e];
    bool k0 = (u0 + KEEP_PROB >= 1.0f);
    bool k1 = (u1 + KEEP_PROB >= 1.0f);
    if (!k0 && !k1) return;
    int r = rows[e];
    int c = cols[e];
    float v = vals[e] / KEEP_PROB;
    ull add = (k0 ? 1ULL : 0ULL) + (k1 ? (1ULL << 32) : 0ULL);
    ull old = atomicAdd(&g_cur[r], add);
    int2 pay = make_int2(c, __float_as_int(v));
    if (k0) g_e0[(int)(old & 0xffffffffULL)] = pay;
    if (k1) g_e1[(int)(old >> 32)] = pay;
}

// ---------------------------------------------------------------------------
// FC: out[n][d] = sum_k emb[n][k] * W[d][k] + b[d]  (unchanged, passing)
// ---------------------------------------------------------------------------
__global__ void fc_kernel(const float* __restrict__ emb,
                          const float* __restrict__ W,
                          const float* __restrict__ b,
                          float* __restrict__ out) {
    __shared__ float Ws[64 * 65];
    __shared__ float bs[64];
    __shared__ float es[4 * 64];

    int tid = threadIdx.x;
    #pragma unroll
    for (int i = tid; i < 64 * 64; i += 256) {
        int d = i >> 6, k = i & 63;
        Ws[d * 65 + k] = W[i];
    }
    if (tid < 64) bs[tid] = b[tid];

    int n0 = blockIdx.x * 4;
    es[tid] = emb[(size_t)n0 * D + tid];
    __syncthreads();

    int nl = tid >> 6;
    int d  = tid & 63;
    const float* er = &es[nl * 64];
    const float* wr = &Ws[d * 65];
    float sum = bs[d];
    #pragma unroll
    for (int k = 0; k < 64; k++) sum = fmaf(er[k], wr[k], sum);
    out[(size_t)(n0 + nl) * D + d] = sum;
}

// ---------------------------------------------------------------------------
// 5) CSR SpMM consume: 64 threads per node, thread d owns dim d.
//    Broadcast 8B edge payload + fully-coalesced 256B row gather, register acc.
//    LAYER==0: x = all_emb,  write g_x1.
//    LAYER==1: x = g_x1,     fused finalize: out = (fc_out + x1 + acc)/3.
// ---------------------------------------------------------------------------
template <int LAYER>
__global__ void csr_spmm_kernel(const float* __restrict__ x_ext,
                                float* __restrict__ out) {
    int n = blockIdx.x * 4 + (threadIdx.x >> 6);
    int d = threadIdx.x & 63;

    const float* __restrict__ x = (LAYER == 0) ? x_ext : g_x1;
    const int2*  __restrict__ ed = (LAYER == 0) ? g_e0 : g_e1;

    ull o0 = g_off[n];
    ull o1 = g_off[n + 1];
    int s, e;
    if (LAYER == 0) { s = (int)(o0 & 0xffffffffULL); e = (int)(o1 & 0xffffffffULL); }
    else            { s = (int)(o0 >> 32);           e = (int)(o1 >> 32);           }

    float acc = 0.0f;
    int i = s;
    // 2-edge unroll for MLP on the gathers
    for (; i + 2 <= e; i += 2) {
        int2 a = ed[i];
        int2 b = ed[i + 1];
        float xa = x[a.x * D + d];
        float xb = x[b.x * D + d];
        acc = fmaf(__int_as_float(a.y), xa, acc);
        acc = fmaf(__int_as_float(b.y), xb, acc);
    }
    if (i < e) {
        int2 a = ed[i];
        acc = fmaf(__int_as_float(a.y), x[a.x * D + d], acc);
    }

    int idx = n * D + d;
    if (LAYER == 0) {
        g_x1[idx] = acc;
    } else {
        out[idx] = (out[idx] + x[idx] + acc) * (1.0f / 3.0f);
    }
}

// ---------------------------------------------------------------------------
extern "C" void kernel_launch(void* const* d_in, const int* in_sizes, int n_in,
                              void* d_out, int out_size) {
    const float* all_emb = (const float*)d_in[0];
    const float* W       = (const float*)d_in[1];
    const float* b       = (const float*)d_in[2];
    const float* vals    = (const float*)d_in[3];
    const float* drop_u  = (const float*)d_in[4];
    const int*   rows    = (const int*)d_in[5];
    const int*   cols    = (const int*)d_in[6];
    float* out = (float*)d_out;

    const int EDGE_BLOCKS = (N_EDGES + 255) / 256;   // 4688
    const int NODE_BLOCKS = (N_NODES + 255) / 256;   // 391

    // CSR build (both layers at once, packed u64)
    zero_cnt_kernel<<<NODE_BLOCKS, 256>>>();
    count_kernel<<<EDGE_BLOCKS, 256>>>(rows, drop_u);
    scan_part_kernel<<<NUM_SBLK, 256>>>();
    scan_top_kernel<<<1, 64>>>();
    scan_add_kernel<<<NODE_BLOCKS, 256>>>();
    scatter_kernel<<<EDGE_BLOCKS, 256>>>(rows, cols, vals, drop_u);

    // fc -> out (unscaled)
    fc_kernel<<<N_NODES / 4, 256>>>(all_emb, W, b, out);

    // layer 0: g_x1 = A0 @ all_emb
    csr_spmm_kernel<0><<<N_NODES / 4, 256>>>(all_emb, out);
    // layer 1 + fused finalize: out = (fc + x1 + A1 @ x1) / 3
    csr_spmm_kernel<1><<<N_NODES / 4, 256>>>(nullptr, out);
}

// round 9
// speedup vs baseline: 1.9639x; 1.2763x over previous
#include <cuda_runtime.h>
#include <cuda_bf16.h>
#include <cstdint>

#define N_NODES 100000
#define N_EDGES 1200000
#define D 64
#define KEEP_PROB 0.7f
#define SCAN_CHUNK 2048
#define NUM_SBLK ((N_NODES + SCAN_CHUNK - 1) / SCAN_CHUNK)  // 49

typedef unsigned long long ull;

// ---------------------------------------------------------------------------
// Scratch (__device__ globals per alloc rules).
// Packed: low 32 bits = layer 0, high 32 bits = layer 1.
// ---------------------------------------------------------------------------
__device__ ull  g_cnt[N_NODES];
__device__ ull  g_off[N_NODES + 1];
__device__ ull  g_cur[N_NODES];
__device__ ull  g_bsum[NUM_SBLK];
__device__ int2 g_e0[N_EDGES];
__device__ int2 g_e1[N_EDGES];
__device__ float g_x1[(size_t)N_NODES * D];

// ---------------------------------------------------------------------------
__global__ void zero_cnt_kernel() {
    int i = blockIdx.x * blockDim.x + threadIdx.x;
    if (i < N_NODES) g_cnt[i] = 0ULL;
}

__global__ void count_kernel(const int* __restrict__ rows,
                             const float* __restrict__ du) {
    int e = blockIdx.x * blockDim.x + threadIdx.x;
    if (e >= N_EDGES) return;
    float u0 = du[e];
    float u1 = du[N_EDGES + e];
    ull add = 0ULL;
    if (u0 + KEEP_PROB >= 1.0f) add += 1ULL;
    if (u1 + KEEP_PROB >= 1.0f) add += (1ULL << 32);
    if (add) atomicAdd(&g_cnt[rows[e]], add);
}

// ---------------------------------------------------------------------------
__global__ void scan_part_kernel() {
    __shared__ ull wt[8];
    __shared__ ull wtot;
    int tid = threadIdx.x;
    int lane = tid & 31, wid = tid >> 5;
    int base = blockIdx.x * SCAN_CHUNK + tid * 8;

    ull v[8]; ull sum = 0ULL;
    #pragma unroll
    for (int j = 0; j < 8; j++) {
        int idx = base + j;
        v[j] = (idx < N_NODES) ? g_cnt[idx] : 0ULL;
        sum += v[j];
    }
    ull s = sum;
    #pragma unroll
    for (int o = 1; o < 32; o <<= 1) {
        ull t = __shfl_up_sync(0xffffffffu, s, o);
        if (lane >= o) s += t;
    }
    if (lane == 31) wt[wid] = s;
    __syncthreads();
    if (tid == 0) {
        ull r = 0ULL;
        #pragma unroll
        for (int k = 0; k < 8; k++) { ull t = wt[k]; wt[k] = r; r += t; }
        wtot = r;
    }
    __syncthreads();

    ull run = wt[wid] + (s - sum);
    #pragma unroll
    for (int j = 0; j < 8; j++) {
        int idx = base + j;
        if (idx < N_NODES) g_off[idx] = run;
        run += v[j];
    }
    if (tid == 0) g_bsum[blockIdx.x] = wtot;
}

__global__ void scan_top_kernel() {
    __shared__ ull s[NUM_SBLK];
    int tid = threadIdx.x;
    if (tid < NUM_SBLK) s[tid] = g_bsum[tid];
    __syncthreads();
    if (tid == 0) {
        ull r = 0ULL;
        for (int k = 0; k < NUM_SBLK; k++) { ull t = s[k]; g_bsum[k] = r; r += t; }
        g_off[N_NODES] = r;
    }
}

__global__ void scan_add_kernel() {
    int i = blockIdx.x * blockDim.x + threadIdx.x;
    if (i < N_NODES) {
        ull o = g_off[i] + g_bsum[i / SCAN_CHUNK];
        g_off[i] = o;
        g_cur[i] = o;
    }
}

// ---------------------------------------------------------------------------
__global__ void scatter_kernel(const int* __restrict__ rows,
                               const int* __restrict__ cols,
                               const float* __restrict__ vals,
                               const float* __restrict__ du) {
    int e = blockIdx.x * blockDim.x + threadIdx.x;
    if (e >= N_EDGES) return;
    float u0 = du[e];
    float u1 = du[N_EDGES + e];
    bool k0 = (u0 + KEEP_PROB >= 1.0f);
    bool k1 = (u1 + KEEP_PROB >= 1.0f);
    if (!k0 && !k1) return;
    int r = rows[e];
    int c = cols[e];
    float v = vals[e] / KEEP_PROB;
    ull add = (k0 ? 1ULL : 0ULL) + (k1 ? (1ULL << 32) : 0ULL);
    ull old = atomicAdd(&g_cur[r], add);
    int2 pay = make_int2(c, __float_as_int(v));
    if (k0) g_e0[(int)(old & 0xffffffffULL)] = pay;
    if (k1) g_e1[(int)(old >> 32)] = pay;
}

// ---------------------------------------------------------------------------
// FC v2: register-tiled GEMM. Block = 256 threads, 64 nodes.
// Each thread computes a 4-node x 4-dim tile. W and emb tiles stored k-major
// (pad 68) so each k-step is two LDS.128 feeding 16 FMAs.
// out[n][d] = sum_k emb[n][k] * W[d][k] + b[d]
// ---------------------------------------------------------------------------
__global__ void __launch_bounds__(256) fc2_kernel(
        const float* __restrict__ emb,
        const float* __restrict__ W,
        const float* __restrict__ b,
        float* __restrict__ out) {
    __shared__ float Wt[64 * 68];   // Wt[k*68 + d]
    __shared__ float et[64 * 68];   // et[k*68 + local_node]
    __shared__ float bs[64];

    int tid = threadIdx.x;
    int n0 = blockIdx.x * 64;

    if (tid < 64) bs[tid] = b[tid];
    #pragma unroll
    for (int i = tid; i < 4096; i += 256) {
        int r = i >> 6, k = i & 63;        // W[r][k], coalesced read
        Wt[k * 68 + r] = W[i];
        int n = n0 + r;
        et[k * 68 + r] = (n < N_NODES) ? emb[(size_t)n * 64 + k] : 0.0f;
    }
    __syncthreads();

    int tx = tid & 15;        // dim group: dims 4*tx .. 4*tx+3
    int ty = tid >> 4;        // node group: nodes 4*ty .. 4*ty+3
    int d0 = tx * 4;
    int r0 = ty * 4;

    float acc[4][4];
    #pragma unroll
    for (int a = 0; a < 4; a++)
        #pragma unroll
        for (int c = 0; c < 4; c++) acc[a][c] = 0.0f;

    #pragma unroll 4
    for (int k = 0; k < 64; k++) {
        float4 er = *reinterpret_cast<const float4*>(&et[k * 68 + r0]);
        float4 wr = *reinterpret_cast<const float4*>(&Wt[k * 68 + d0]);
        float e4[4] = {er.x, er.y, er.z, er.w};
        float w4[4] = {wr.x, wr.y, wr.z, wr.w};
        #pragma unroll
        for (int a = 0; a < 4; a++)
            #pragma unroll
            for (int c = 0; c < 4; c++)
                acc[a][c] = fmaf(e4[a], w4[c], acc[a][c]);
    }

    #pragma unroll
    for (int a = 0; a < 4; a++) {
        int n = n0 + r0 + a;
        if (n < N_NODES) {
            float4 o;
            o.x = acc[a][0] + bs[d0 + 0];
            o.y = acc[a][1] + bs[d0 + 1];
            o.z = acc[a][2] + bs[d0 + 2];
            o.w = acc[a][3] + bs[d0 + 3];
            *reinterpret_cast<float4*>(&out[(size_t)n * 64 + d0]) = o;
        }
    }
}

// ---------------------------------------------------------------------------
// CSR SpMM consume: 64 threads/node, thread d owns dim d. 4-edge unroll.
// LAYER==0: x = all_emb, write g_x1.
// LAYER==1: x = g_x1, fused finalize: out = (fc + x1 + acc)/3.
// ---------------------------------------------------------------------------
template <int LAYER>
__global__ void csr_spmm_kernel(const float* __restrict__ x_ext,
                                float* __restrict__ out) {
    int n = blockIdx.x * 4 + (threadIdx.x >> 6);
    int d = threadIdx.x & 63;

    const float* __restrict__ x = (LAYER == 0) ? x_ext : g_x1;
    const int2*  __restrict__ ed = (LAYER == 0) ? g_e0 : g_e1;

    ull o0 = g_off[n];
    ull o1 = g_off[n + 1];
    int s, e;
    if (LAYER == 0) { s = (int)(o0 & 0xffffffffULL); e = (int)(o1 & 0xffffffffULL); }
    else            { s = (int)(o0 >> 32);           e = (int)(o1 >> 32);           }

    float acc = 0.0f;
    int i = s;
    for (; i + 4 <= e; i += 4) {
        int2 p0 = ed[i];
        int2 p1 = ed[i + 1];
        int2 p2 = ed[i + 2];
        int2 p3 = ed[i + 3];
        float x0 = x[p0.x * D + d];
        float x1 = x[p1.x * D + d];
        float x2 = x[p2.x * D + d];
        float x3 = x[p3.x * D + d];
        acc = fmaf(__int_as_float(p0.y), x0, acc);
        acc = fmaf(__int_as_float(p1.y), x1, acc);
        acc = fmaf(__int_as_float(p2.y), x2, acc);
        acc = fmaf(__int_as_float(p3.y), x3, acc);
    }
    for (; i < e; i++) {
        int2 p = ed[i];
        acc = fmaf(__int_as_float(p.y), x[p.x * D + d], acc);
    }

    int idx = n * D + d;
    if (LAYER == 0) {
        g_x1[idx] = acc;
    } else {
        out[idx] = (out[idx] + x[idx] + acc) * (1.0f / 3.0f);
    }
}

// ---------------------------------------------------------------------------
extern "C" void kernel_launch(void* const* d_in, const int* in_sizes, int n_in,
                              void* d_out, int out_size) {
    const float* all_emb = (const float*)d_in[0];
    const float* W       = (const float*)d_in[1];
    const float* b       = (const float*)d_in[2];
    const float* vals    = (const float*)d_in[3];
    const float* drop_u  = (const float*)d_in[4];
    const int*   rows    = (const int*)d_in[5];
    const int*   cols    = (const int*)d_in[6];
    float* out = (float*)d_out;

    const int EDGE_BLOCKS = (N_EDGES + 255) / 256;   // 4688
    const int NODE_BLOCKS = (N_NODES + 255) / 256;   // 391

    // CSR build (both layers at once, packed u64)
    zero_cnt_kernel<<<NODE_BLOCKS, 256>>>();
    count_kernel<<<EDGE_BLOCKS, 256>>>(rows, drop_u);
    scan_part_kernel<<<NUM_SBLK, 256>>>();
    scan_top_kernel<<<1, 64>>>();
    scan_add_kernel<<<NODE_BLOCKS, 256>>>();
    scatter_kernel<<<EDGE_BLOCKS, 256>>>(rows, cols, vals, drop_u);

    // fc -> out (unscaled), register-tiled
    fc2_kernel<<<(N_NODES + 63) / 64, 256>>>(all_emb, W, b, out);

    // layer 0: g_x1 = A0 @ all_emb
    csr_spmm_kernel<0><<<N_NODES / 4, 256>>>(all_emb, out);
    // layer 1 + fused finalize: out = (fc + x1 + A1 @ x1) / 3
    csr_spmm_kernel<1><<<N_NODES / 4, 256>>>(nullptr, out);
}

// round 10
// speedup vs baseline: 2.6583x; 1.3535x over previous
#include <cuda_runtime.h>
#include <cuda_bf16.h>
#include <cstdint>

#define N_NODES 100000
#define N_EDGES 1200000
#define D 64
#define KEEP_PROB 0.7f
#define SCAN_CHUNK 2048
#define NUM_SBLK ((N_NODES + SCAN_CHUNK - 1) / SCAN_CHUNK)  // 49

typedef unsigned long long ull;

// ---- packed f32x2 helpers (Blackwell FFMA2 via PTX; ptxas won't auto-fuse) ----
__device__ __forceinline__ ull pk2(float a, float b) {
    ull r; asm("mov.b64 %0, {%1, %2};" : "=l"(r) : "f"(a), "f"(b)); return r;
}
__device__ __forceinline__ ull fma2(ull a, ull b, ull c) {
    ull d; asm("fma.rn.f32x2 %0, %1, %2, %3;" : "=l"(d) : "l"(a), "l"(b), "l"(c)); return d;
}
__device__ __forceinline__ ull add2(ull a, ull b) {
    ull d; asm("add.rn.f32x2 %0, %1, %2;" : "=l"(d) : "l"(a), "l"(b)); return d;
}
__device__ __forceinline__ ull mul2(ull a, ull b) {
    ull d; asm("mul.rn.f32x2 %0, %1, %2;" : "=l"(d) : "l"(a), "l"(b)); return d;
}
__device__ __forceinline__ void upk2(ull v, float& lo, float& hi) {
    asm("mov.b64 {%0, %1}, %2;" : "=f"(lo), "=f"(hi) : "l"(v));
}

// ---------------------------------------------------------------------------
// Scratch (__device__ globals per alloc rules).
// Packed: low 32 bits = layer 0, high 32 bits = layer 1.
// ---------------------------------------------------------------------------
__device__ ull  g_cnt[N_NODES];
__device__ ull  g_off[N_NODES + 1];
__device__ ull  g_cur[N_NODES];
__device__ ull  g_bsum[NUM_SBLK];
__device__ int2 g_e0[N_EDGES];
__device__ int2 g_e1[N_EDGES];
__device__ float g_x1[(size_t)N_NODES * D];

// ---------------------------------------------------------------------------
__global__ void zero_cnt_kernel() {
    int i = blockIdx.x * blockDim.x + threadIdx.x;
    if (i < N_NODES) g_cnt[i] = 0ULL;
}

__global__ void count_kernel(const int* __restrict__ rows,
                             const float* __restrict__ du) {
    int e = blockIdx.x * blockDim.x + threadIdx.x;
    if (e >= N_EDGES) return;
    float u0 = du[e];
    float u1 = du[N_EDGES + e];
    ull add = 0ULL;
    if (u0 + KEEP_PROB >= 1.0f) add += 1ULL;
    if (u1 + KEEP_PROB >= 1.0f) add += (1ULL << 32);
    if (add) atomicAdd(&g_cnt[rows[e]], add);
}

// ---------------------------------------------------------------------------
// scan part: per-2048-chunk exclusive scan into g_off, chunk total -> g_bsum
// ---------------------------------------------------------------------------
__global__ void scan_part_kernel() {
    __shared__ ull wt[8];
    __shared__ ull wtot;
    int tid = threadIdx.x;
    int lane = tid & 31, wid = tid >> 5;
    int base = blockIdx.x * SCAN_CHUNK + tid * 8;

    ull v[8]; ull sum = 0ULL;
    #pragma unroll
    for (int j = 0; j < 8; j++) {
        int idx = base + j;
        v[j] = (idx < N_NODES) ? g_cnt[idx] : 0ULL;
        sum += v[j];
    }
    ull s = sum;
    #pragma unroll
    for (int o = 1; o < 32; o <<= 1) {
        ull t = __shfl_up_sync(0xffffffffu, s, o);
        if (lane >= o) s += t;
    }
    if (lane == 31) wt[wid] = s;
    __syncthreads();
    if (tid == 0) {
        ull r = 0ULL;
        #pragma unroll
        for (int k = 0; k < 8; k++) { ull t = wt[k]; wt[k] = r; r += t; }
        wtot = r;
    }
    __syncthreads();

    ull run = wt[wid] + (s - sum);
    #pragma unroll
    for (int j = 0; j < 8; j++) {
        int idx = base + j;
        if (idx < N_NODES) g_off[idx] = run;
        run += v[j];
    }
    if (tid == 0) g_bsum[blockIdx.x] = wtot;
}

// ---------------------------------------------------------------------------
// fused top+add: every block redundantly prefixes the 49 chunk totals in smem
// (49 loads, trivial), then applies its chunk prefix and inits the cursors.
// Also writes the grand total into g_off[N_NODES].
// ---------------------------------------------------------------------------
__global__ void scan_add2_kernel() {
    __shared__ ull pre[NUM_SBLK];
    int tid = threadIdx.x;
    if (tid < NUM_SBLK) pre[tid] = g_bsum[tid];
    __syncthreads();
    if (tid == 0) {
        ull r = 0ULL;
        #pragma unroll
        for (int k = 0; k < NUM_SBLK; k++) { ull t = pre[k]; pre[k] = r; r += t; }
    }
    __syncthreads();
    int i = blockIdx.x * blockDim.x + tid;
    if (i < N_NODES) {
        ull o = g_off[i] + pre[i / SCAN_CHUNK];
        g_off[i] = o;
        g_cur[i] = o;
        if (i == N_NODES - 1) g_off[N_NODES] = o + g_cnt[i];
    }
}

// ---------------------------------------------------------------------------
__global__ void scatter_kernel(const int* __restrict__ rows,
                               const int* __restrict__ cols,
                               const float* __restrict__ vals,
                               const float* __restrict__ du) {
    int e = blockIdx.x * blockDim.x + threadIdx.x;
    if (e >= N_EDGES) return;
    float u0 = du[e];
    float u1 = du[N_EDGES + e];
    bool k0 = (u0 + KEEP_PROB >= 1.0f);
    bool k1 = (u1 + KEEP_PROB >= 1.0f);
    if (!k0 && !k1) return;
    int r = rows[e];
    int c = cols[e];
    float v = vals[e] / KEEP_PROB;
    ull add = (k0 ? 1ULL : 0ULL) + (k1 ? (1ULL << 32) : 0ULL);
    ull old = atomicAdd(&g_cur[r], add);
    int2 pay = make_int2(c, __float_as_int(v));
    if (k0) g_e0[(int)(old & 0xffffffffULL)] = pay;
    if (k1) g_e1[(int)(old >> 32)] = pay;
}

// ---------------------------------------------------------------------------
// FC v3: register-tiled GEMM with packed FFMA2.
// Block = 256 threads, 64 nodes; thread tile = 4 nodes x 4 dims (as 2 f32x2).
// out[n][d] = sum_k emb[n][k] * W[d][k] + b[d]
// ---------------------------------------------------------------------------
__global__ void __launch_bounds__(256) fc3_kernel(
        const float* __restrict__ emb,
        const float* __restrict__ W,
        const float* __restrict__ b,
        float* __restrict__ out) {
    __shared__ float Wt[64 * 68];   // Wt[k*68 + d]
    __shared__ float et[64 * 68];   // et[k*68 + local_node]
    __shared__ float bs[64];

    int tid = threadIdx.x;
    int n0 = blockIdx.x * 64;

    if (tid < 64) bs[tid] = b[tid];
    #pragma unroll
    for (int i = tid; i < 4096; i += 256) {
        int r = i >> 6, k = i & 63;        // W[r][k], coalesced read
        Wt[k * 68 + r] = W[i];
        int n = n0 + r;
        et[k * 68 + r] = (n < N_NODES) ? emb[(size_t)n * 64 + k] : 0.0f;
    }
    __syncthreads();

    int tx = tid & 15;        // dim group: dims 4*tx .. 4*tx+3
    int ty = tid >> 4;        // node group: nodes 4*ty .. 4*ty+3
    int d0 = tx * 4;
    int r0 = ty * 4;

    ull acc01[4], acc23[4];
    #pragma unroll
    for (int a = 0; a < 4; a++) { acc01[a] = 0ULL; acc23[a] = 0ULL; }

    #pragma unroll 4
    for (int k = 0; k < 64; k++) {
        float4 er = *reinterpret_cast<const float4*>(&et[k * 68 + r0]);
        float4 wr = *reinterpret_cast<const float4*>(&Wt[k * 68 + d0]);
        ull w01 = pk2(wr.x, wr.y);
        ull w23 = pk2(wr.z, wr.w);
        float e4[4] = {er.x, er.y, er.z, er.w};
        #pragma unroll
        for (int a = 0; a < 4; a++) {
            ull e2 = pk2(e4[a], e4[a]);
            acc01[a] = fma2(e2, w01, acc01[a]);
            acc23[a] = fma2(e2, w23, acc23[a]);
        }
    }

    #pragma unroll
    for (int a = 0; a < 4; a++) {
        int n = n0 + r0 + a;
        if (n < N_NODES) {
            float4 o;
            upk2(acc01[a], o.x, o.y);
            upk2(acc23[a], o.z, o.w);
            o.x += bs[d0 + 0];
            o.y += bs[d0 + 1];
            o.z += bs[d0 + 2];
            o.w += bs[d0 + 3];
            *reinterpret_cast<float4*>(&out[(size_t)n * 64 + d0]) = o;
        }
    }
}

// ---------------------------------------------------------------------------
// CSR SpMM consume v2: ONE WARP per node, each lane owns 2 dims (f32x2).
// Per edge: 1 broadcast LDG.64 payload + 1 coalesced LDG.64 gather + 1 FFMA2.
// LAYER==0: x = all_emb, write g_x1.
// LAYER==1: x = g_x1, fused finalize: out = (fc + x1 + acc)/3.
// ---------------------------------------------------------------------------
template <int LAYER>
__global__ void __launch_bounds__(256) csr_spmm2_kernel(
        const float* __restrict__ x_ext,
        float* __restrict__ out) {
    int n = blockIdx.x * 8 + (threadIdx.x >> 5);
    int lane = threadIdx.x & 31;

    const float* __restrict__ xf = (LAYER == 0) ? x_ext : g_x1;
    const ull* __restrict__ x2 = reinterpret_cast<const ull*>(xf);
    const int2* __restrict__ ed = (LAYER == 0) ? g_e0 : g_e1;

    ull o0 = g_off[n];
    ull o1 = g_off[n + 1];
    int s, e;
    if (LAYER == 0) { s = (int)(o0 & 0xffffffffULL); e = (int)(o1 & 0xffffffffULL); }
    else            { s = (int)(o0 >> 32);           e = (int)(o1 >> 32);           }

    ull acc = 0ULL;
    int i = s;
    for (; i + 4 <= e; i += 4) {
        int2 p0 = ed[i];
        int2 p1 = ed[i + 1];
        int2 p2 = ed[i + 2];
        int2 p3 = ed[i + 3];
        ull xv0 = x2[p0.x * 32 + lane];
        ull xv1 = x2[p1.x * 32 + lane];
        ull xv2 = x2[p2.x * 32 + lane];
        ull xv3 = x2[p3.x * 32 + lane];
        float v0 = __int_as_float(p0.y);
        float v1 = __int_as_float(p1.y);
        float v2 = __int_as_float(p2.y);
        float v3 = __int_as_float(p3.y);
        acc = fma2(pk2(v0, v0), xv0, acc);
        acc = fma2(pk2(v1, v1), xv1, acc);
        acc = fma2(pk2(v2, v2), xv2, acc);
        acc = fma2(pk2(v3, v3), xv3, acc);
    }
    for (; i < e; i++) {
        int2 p = ed[i];
        float v = __int_as_float(p.y);
        acc = fma2(pk2(v, v), x2[p.x * 32 + lane], acc);
    }

    size_t idx = (size_t)n * 32 + lane;
    if (LAYER == 0) {
        reinterpret_cast<ull*>(g_x1)[idx] = acc;
    } else {
        ull* o2 = reinterpret_cast<ull*>(out);
        ull fcv = o2[idx];
        ull x1v = x2[idx];
        ull sum = add2(add2(fcv, x1v), acc);
        const float third = 1.0f / 3.0f;
        o2[idx] = mul2(sum, pk2(third, third));
    }
}

// ---------------------------------------------------------------------------
extern "C" void kernel_launch(void* const* d_in, const int* in_sizes, int n_in,
                              void* d_out, int out_size) {
    const float* all_emb = (const float*)d_in[0];
    const float* W       = (const float*)d_in[1];
    const float* b       = (const float*)d_in[2];
    const float* vals    = (const float*)d_in[3];
    const float* drop_u  = (const float*)d_in[4];
    const int*   rows    = (const int*)d_in[5];
    const int*   cols    = (const int*)d_in[6];
    float* out = (float*)d_out;

    const int EDGE_BLOCKS = (N_EDGES + 255) / 256;   // 4688
    const int NODE_BLOCKS = (N_NODES + 255) / 256;   // 391

    // CSR build (both layers at once, packed u64)
    zero_cnt_kernel<<<NODE_BLOCKS, 256>>>();
    count_kernel<<<EDGE_BLOCKS, 256>>>(rows, drop_u);
    scan_part_kernel<<<NUM_SBLK, 256>>>();
    scan_add2_kernel<<<NODE_BLOCKS, 256>>>();
    scatter_kernel<<<EDGE_BLOCKS, 256>>>(rows, cols, vals, drop_u);

    // fc -> out (unscaled), register-tiled + FFMA2
    fc3_kernel<<<(N_NODES + 63) / 64, 256>>>(all_emb, W, b, out);

    // layer 0: g_x1 = A0 @ all_emb
    csr_spmm2_kernel<0><<<N_NODES / 8, 256>>>(all_emb, out);
    // layer 1 + fused finalize: out = (fc + x1 + A1 @ x1) / 3
    csr_spmm2_kernel<1><<<N_NODES / 8, 256>>>(nullptr, out);
}